// round 8
// baseline (speedup 1.0000x reference)
#include <cuda_runtime.h>
#include <cuda_bf16.h>
#include <cstdint>

#define D            128
#define S            16
#define BMAX         8192

// ---------------- scratch (device globals: allocation-free) ----------------
__device__ float g_x0 [BMAX * D];   // msg + rep0 (GEMM input, fp32)
__device__ float g_msg[BMAX * D];   // msg (residual adds, fp32)

// ============================ kernel 1: gather =============================
// One warp per item. No smem. 32 warps/SM -> deep gather MLP.
__global__ __launch_bounds__(256, 4)
void gather_kernel(const int* __restrict__ u,
                   const int* __restrict__ v,
                   const int* __restrict__ adj_ent,
                   const int* __restrict__ adj_rel,
                   const float* __restrict__ usr,
                   const float* __restrict__ ent,
                   const float* __restrict__ rel,
                   int B)
{
    const int lane = threadIdx.x & 31;
    const int item = blockIdx.x * 8 + (threadIdx.x >> 5);
    if (item >= B) return;

    const float4* usr4 = (const float4*)usr;
    const float4* ent4 = (const float4*)ent;
    const float4* rel4 = (const float4*)rel;
    const int4*   adjE4 = (const int4*)adj_ent;
    const int4*   adjR4 = (const int4*)adj_rel;

    const int iu = u[item];
    const int iv = v[item];

    const float4 uex = usr4[(size_t)iu * 32 + lane];
    const float4 rp  = ent4[(size_t)iv * 32 + lane];

    int eix[S], rix[S];
    #pragma unroll
    for (int q = 0; q < 4; q++) {
        const int4 e = __ldg(&adjE4[iv * 4 + q]);
        const int4 r = __ldg(&adjR4[iv * 4 + q]);
        eix[q*4+0] = e.x; eix[q*4+1] = e.y; eix[q*4+2] = e.z; eix[q*4+3] = e.w;
        rix[q*4+0] = r.x; rix[q*4+1] = r.y; rix[q*4+2] = r.z; rix[q*4+3] = r.w;
    }

    // fused single-pass attention (scores tiny; no-max-sub exp validated)
    float sum = 0.f;
    float4 msg = make_float4(0.f, 0.f, 0.f, 0.f);
    #pragma unroll
    for (int s = 0; s < S; s++) {
        const float4 r4 = rel4[(size_t)rix[s] * 32 + lane];
        const float4 e4 = ent4[(size_t)eix[s] * 32 + lane];
        float p = uex.x * r4.x + uex.y * r4.y + uex.z * r4.z + uex.w * r4.w;
        #pragma unroll
        for (int o = 16; o > 0; o >>= 1)
            p += __shfl_xor_sync(0xffffffffu, p, o);
        const float es = __expf(p);
        sum += es;
        msg.x = fmaf(es, e4.x, msg.x);
        msg.y = fmaf(es, e4.y, msg.y);
        msg.z = fmaf(es, e4.z, msg.z);
        msg.w = fmaf(es, e4.w, msg.w);
    }
    const float inv = __frcp_rn(sum);
    msg.x *= inv; msg.y *= inv; msg.z *= inv; msg.w *= inv;

    ((float4*)(g_msg + item * D))[lane] = msg;
    ((float4*)(g_x0  + item * D))[lane] =
        make_float4(msg.x + rp.x, msg.y + rp.y, msg.z + rp.z, msg.w + rp.w);
}

// ============================ kernel 2: GEMM ===============================
#define WARPS_PB     8
#define ITEM_TILE    4
#define ITEMS_PB     32
#define BLOCK_THREADS 256
#define WSTRIDE      136
#define XSTRIDE      132
#define W_FLOATS     (D * WSTRIDE)
#define X_FLOATS     (ITEMS_PB * XSTRIDE)
#define SMEM_BYTES   ((W_FLOATS + 2 * X_FLOATS) * 4)   // 103424 -> 2 blocks/SM

__device__ __forceinline__ uint32_t f2tf32(float f) {
    uint32_t r;
    asm("cvt.rna.tf32.f32 %0, %1;" : "=r"(r) : "f"(f));
    return r;
}
__device__ __forceinline__ void mma_tf32(float acc[4], const uint32_t a[4],
                                         const uint32_t b[2]) {
    asm("mma.sync.aligned.m16n8k8.row.col.f32.tf32.tf32.f32 "
        "{%0,%1,%2,%3}, {%4,%5,%6,%7}, {%8,%9}, {%0,%1,%2,%3};"
        : "+f"(acc[0]), "+f"(acc[1]), "+f"(acc[2]), "+f"(acc[3])
        : "r"(a[0]), "r"(a[1]), "r"(a[2]), "r"(a[3]),
          "r"(b[0]), "r"(b[1]));
}

__global__ __launch_bounds__(BLOCK_THREADS, 2)
void gemm_kernel(const int* __restrict__ u,
                 const float* __restrict__ usr,
                 const float* __restrict__ W,
                 const float* __restrict__ bias,
                 float* __restrict__ out,
                 int B)
{
    extern __shared__ char smraw[];
    uint32_t* Wsh = (uint32_t*)smraw;                           // tf32 W [128][136]
    uint32_t* Xsh = (uint32_t*)(smraw + W_FLOATS * 4);          // tf32 X [32][132]
    float*    Msh = (float*)   (smraw + (W_FLOATS + X_FLOATS) * 4);
    float*    Hsh = Msh;

    const int tid  = threadIdx.x;
    const int lane = tid & 31;
    const int wid  = tid >> 5;
    const int g    = lane >> 2;
    const int tq   = lane & 3;

    // stage W -> shared (tf32, padded)
    {
        const float4* Wg4 = (const float4*)W;
        #pragma unroll
        for (int k = 0; k < (D * D / 4) / BLOCK_THREADS; k++) {
            const int i = tid + k * BLOCK_THREADS;
            const float4 w = Wg4[i];
            const int row = (i * 4) >> 7;
            const int col = (i * 4) & 127;
            uint32_t* p = Wsh + row * WSTRIDE + col;
            p[0] = f2tf32(w.x); p[1] = f2tf32(w.y);
            p[2] = f2tf32(w.z); p[3] = f2tf32(w.w);
        }
    }

    const int base = (blockIdx.x * WARPS_PB + wid) * ITEM_TILE;

    // stage X (tf32) and msg (fp32) from scratch, coalesced
    #pragma unroll
    for (int t = 0; t < ITEM_TILE; t++) {
        const int item = base + t;
        const int cit  = item < B ? item : (B - 1);
        const int row  = wid * ITEM_TILE + t;
        const float4 x = ((const float4*)(g_x0  + cit * D))[lane];
        const float4 m = ((const float4*)(g_msg + cit * D))[lane];
        uint32_t* xp = Xsh + row * XSTRIDE + lane * 4;
        xp[0] = f2tf32(x.x); xp[1] = f2tf32(x.y);
        xp[2] = f2tf32(x.z); xp[3] = f2tf32(x.w);
        ((float4*)(Msh + row * XSTRIDE))[lane] = m;
    }
    __syncthreads();

    // block GEMM M=32, N=128, K=128; warp owns 16 N-cols
    const int ncol0 = wid * 16;
    float bb[2][2];
    #pragma unroll
    for (int nt = 0; nt < 2; nt++) {
        bb[nt][0] = __ldg(&bias[ncol0 + nt * 8 + tq * 2]);
        bb[nt][1] = __ldg(&bias[ncol0 + nt * 8 + tq * 2 + 1]);
    }

    float acc[2][2][4];

    #pragma unroll
    for (int iter = 0; iter < 2; iter++) {
        #pragma unroll
        for (int mt = 0; mt < 2; mt++)
            #pragma unroll
            for (int nt = 0; nt < 2; nt++) {
                acc[mt][nt][0] = bb[nt][0]; acc[mt][nt][1] = bb[nt][1];
                acc[mt][nt][2] = bb[nt][0]; acc[mt][nt][3] = bb[nt][1];
            }

        #pragma unroll 4
        for (int kt = 0; kt < 16; kt++) {
            uint32_t a[2][4];
            #pragma unroll
            for (int mt = 0; mt < 2; mt++) {
                const uint32_t* xb = Xsh + (mt * 16 + g) * XSTRIDE + kt * 8 + tq;
                a[mt][0] = xb[0];
                a[mt][1] = xb[8 * XSTRIDE];
                a[mt][2] = xb[4];
                a[mt][3] = xb[8 * XSTRIDE + 4];
            }
            uint32_t b[2][2];
            #pragma unroll
            for (int nt = 0; nt < 2; nt++) {
                const uint32_t* wb = Wsh + (kt * 8 + tq) * WSTRIDE + ncol0 + nt * 8 + g;
                b[nt][0] = wb[0];
                b[nt][1] = wb[4 * WSTRIDE];
            }
            #pragma unroll
            for (int mt = 0; mt < 2; mt++)
                #pragma unroll
                for (int nt = 0; nt < 2; nt++)
                    mma_tf32(acc[mt][nt], a[mt], b[nt]);
        }

        __syncthreads();

        if (iter == 0) {
            #pragma unroll
            for (int mt = 0; mt < 2; mt++) {
                #pragma unroll
                for (int nt = 0; nt < 2; nt++) {
                    const int c0 = ncol0 + nt * 8 + tq * 2;
                    const int r0 = mt * 16 + g;
                    const int r1 = r0 + 8;
                    Xsh[r0 * XSTRIDE + c0    ] = f2tf32(Msh[r0 * XSTRIDE + c0    ] + fmaxf(acc[mt][nt][0], 0.f));
                    Xsh[r0 * XSTRIDE + c0 + 1] = f2tf32(Msh[r0 * XSTRIDE + c0 + 1] + fmaxf(acc[mt][nt][1], 0.f));
                    Xsh[r1 * XSTRIDE + c0    ] = f2tf32(Msh[r1 * XSTRIDE + c0    ] + fmaxf(acc[mt][nt][2], 0.f));
                    Xsh[r1 * XSTRIDE + c0 + 1] = f2tf32(Msh[r1 * XSTRIDE + c0 + 1] + fmaxf(acc[mt][nt][3], 0.f));
                }
            }
            __syncthreads();
        }
    }

    // rep2 = relu(h2) -> Hsh (fp32)
    #pragma unroll
    for (int mt = 0; mt < 2; mt++) {
        #pragma unroll
        for (int nt = 0; nt < 2; nt++) {
            const int c0 = ncol0 + nt * 8 + tq * 2;
            const int r0 = mt * 16 + g;
            const int r1 = r0 + 8;
            Hsh[r0 * XSTRIDE + c0    ] = fmaxf(acc[mt][nt][0], 0.f);
            Hsh[r0 * XSTRIDE + c0 + 1] = fmaxf(acc[mt][nt][1], 0.f);
            Hsh[r1 * XSTRIDE + c0    ] = fmaxf(acc[mt][nt][2], 0.f);
            Hsh[r1 * XSTRIDE + c0 + 1] = fmaxf(acc[mt][nt][3], 0.f);
        }
    }
    __syncthreads();

    // epilogue: sigmoid(dot(u_emb, rep2)); usr rows L2-hot from kernel 1
    const float4* usr4 = (const float4*)usr;
    #pragma unroll
    for (int t = 0; t < ITEM_TILE; t++) {
        const int item = base + t;
        const int cit  = item < B ? item : (B - 1);
        const int iu = u[cit];
        const float4 uex = usr4[(size_t)iu * 32 + lane];
        const int row = wid * ITEM_TILE + t;
        const float4 h = ((const float4*)(Hsh + row * XSTRIDE))[lane];
        float p = uex.x * h.x + uex.y * h.y + uex.z * h.z + uex.w * h.w;
        #pragma unroll
        for (int o = 16; o > 0; o >>= 1)
            p += __shfl_xor_sync(0xffffffffu, p, o);
        if (lane == 0 && item < B)
            out[item] = 1.f / (1.f + __expf(-p));
    }
}

// ================================ launch ===================================
extern "C" void kernel_launch(void* const* d_in, const int* in_sizes, int n_in,
                              void* d_out, int out_size)
{
    const int*   u       = (const int*)d_in[0];
    const int*   v       = (const int*)d_in[1];
    const int*   adj_ent = (const int*)d_in[2];
    const int*   adj_rel = (const int*)d_in[3];
    const float* usr     = (const float*)d_in[4];
    const float* ent     = (const float*)d_in[5];
    const float* rel     = (const float*)d_in[6];
    const float* W       = (const float*)d_in[7];
    const float* bias    = (const float*)d_in[8];
    float* out = (float*)d_out;

    const int B = in_sizes[0];   // 8192

    static bool attr_set = false;
    if (!attr_set) {
        cudaFuncSetAttribute(gemm_kernel,
                             cudaFuncAttributeMaxDynamicSharedMemorySize,
                             SMEM_BYTES);
        attr_set = true;
    }

    dim3 g1((B + 7) / 8);                      // 1024 blocks, 1 warp/item
    gather_kernel<<<g1, 256>>>(u, v, adj_ent, adj_rel, usr, ent, rel, B);

    dim3 g2((B + ITEMS_PB - 1) / ITEMS_PB);    // 256 blocks
    gemm_kernel<<<g2, BLOCK_THREADS, SMEM_BYTES>>>(u, usr, W, bias, out, B);
}